// round 14
// baseline (speedup 1.0000x reference)
#include <cuda_runtime.h>

typedef unsigned long long ull;

#define BATCH 256
#define NTOK  256
#define NFULL 257
#define DIM   768
#define KC    8
#define VCNT  10000
#define ITERS 4
#define NTHREADS 512

#define CHTOK 32                 /* tokens per smem chunk */
#define NCH   8                  /* chunks per pass */
#define TKS   386                /* ull stride per token row (conflict-free banking) */
#define DFS   386                /* ull stride per diff row */
#define BUFULL (CHTOK * TKS)     /* 12352 ull per stage buffer */

/* dynamic smem layout (bytes) — total 229312 < 232448 cap */
#define OFF_TK   0
#define SZ_TK    (2 * BUFULL * 8)          /* 197632 : double-buffered token chunks */
#define OFF_DFT  (OFF_TK + SZ_TK)          /* 197632 */
#define SZ_DFT   (KC * DFS * 8)            /* 24704  : diff[k][dp] */
#define OFF_A2   (OFF_DFT + SZ_DFT)        /* 222336 */
#define SZ_A2    (CHTOK * KC * 8)          /* 2048   : assignments packed (a,a) */
#define OFF_RED  (OFF_A2 + SZ_A2)          /* 224384 */
#define SZ_RED   (4 * 256 * 4)             /* 4096   : phase-A cross-warp partials */
#define OFF_PART (OFF_RED + SZ_RED)        /* 228480 */
#define SZ_PART  (12 * 16 * 4)             /* 768 */
#define OFF_INV  (OFF_PART + SZ_PART)      /* 229248 */
#define KM_SMEM  (OFF_INV + 64)            /* 229312 */

#define FXSCALE     1099511627776.0        /* 2^40 */
#define INV_FXSCALE (1.0 / 1099511627776.0)

__device__ ull g_acc[VCNT];   // fixed-point scatter bins (integer adds: deterministic)

// ---------------- packed f32x2 helpers (sm_103a) ----------------
__device__ __forceinline__ ull ffma2(ull a, ull b, ull c) {
    ull d; asm("fma.rn.f32x2 %0, %1, %2, %3;" : "=l"(d) : "l"(a), "l"(b), "l"(c)); return d;
}
__device__ __forceinline__ ull fadd2(ull a, ull b) {
    ull d; asm("add.rn.f32x2 %0, %1, %2;" : "=l"(d) : "l"(a), "l"(b)); return d;
}
__device__ __forceinline__ ull pack2(float x, float y) {
    ull r; asm("mov.b64 %0, {%1, %2};" : "=l"(r) : "f"(x), "f"(y)); return r;
}
__device__ __forceinline__ void unpack2(ull v, float& x, float& y) {
    asm("mov.b64 {%0, %1}, %2;" : "=f"(x), "=f"(y) : "l"(v));
}

// coalesced cp.async stage of one 32-token chunk (32 x 768 floats), 512 threads
__device__ __forceinline__ void stage_chunk(ull* dstbuf, const float* src, int tid) {
    #pragma unroll
    for (int i = 0; i < 12; ++i) {
        int f = tid + NTHREADS * i;       // 0..6143 16B-segments
        int r = f / 192;                  // token row 0..31
        int s = f - r * 192;              // segment within row
        unsigned d = (unsigned)__cvta_generic_to_shared(dstbuf + r * TKS + s * 2);
        asm volatile("cp.async.cg.shared.global [%0], [%1], 16;"
                     :: "r"(d), "l"(src + (size_t)r * DIM + s * 4));
    }
}

// =====================================================================
// Kernel 1: fused per-batch k-means — R12's proven config (377us).
// 512 threads, 1 block/batch, ~229KB dyn smem -> 1 block/SM.
// =====================================================================
__global__ void __launch_bounds__(NTHREADS, 1)
kmeans_kernel(const float* __restrict__ tokens,
              const float* __restrict__ vc,
              const int*   __restrict__ topk,
              float*       __restrict__ out_assign)
{
    extern __shared__ __align__(16) char smem[];
    ull*   s_tk  = (ull*)(smem + OFF_TK);
    ull*   s_dfT = (ull*)(smem + OFF_DFT);
    ull*   s_a2  = (ull*)(smem + OFF_A2);
    float* s_red = (float*)(smem + OFF_RED);
    float (*s_part)[16] = (float(*)[16])(smem + OFF_PART);
    float* s_inv = (float*)(smem + OFF_INV);

    const int b    = blockIdx.x;
    const int tid  = threadIdx.x;
    const int lane = tid & 31;
    const int w    = tid >> 5;

    const float* tokbase = tokens + ((size_t)b * NFULL + 1) * DIM;

    // prefetch chunk 0 while building the initial diff matrix
    stage_chunk(s_tk, tokbase, tid);
    asm volatile("cp.async.commit_group;");

    // initial diff = c1hat - c0hat (warps 0-7: warp w -> k=w)
    if (w < 8) {
        const int k   = w;
        const int idx = topk[b * KC + k];
        const float4* r0 = (const float4*)(vc + (size_t)idx * 2 * DIM);
        const float4* r1 = r0 + DIM / 4;
        float ss0 = 0.f, ss1 = 0.f;
        for (int j = lane; j < DIM / 4; j += 32) {
            float4 a = r0[j]; ss0 += a.x*a.x + a.y*a.y + a.z*a.z + a.w*a.w;
            float4 c = r1[j]; ss1 += c.x*c.x + c.y*c.y + c.z*c.z + c.w*c.w;
        }
        #pragma unroll
        for (int off = 16; off; off >>= 1) {
            ss0 += __shfl_down_sync(0xffffffffu, ss0, off);
            ss1 += __shfl_down_sync(0xffffffffu, ss1, off);
        }
        ss0 = __shfl_sync(0xffffffffu, ss0, 0);
        ss1 = __shfl_sync(0xffffffffu, ss1, 0);
        const float i0 = 1.f / fmaxf(sqrtf(ss0), 1e-12f);
        const float i1 = 1.f / fmaxf(sqrtf(ss1), 1e-12f);
        const float2* p0 = (const float2*)(vc + (size_t)idx * 2 * DIM);
        const float2* p1 = p0 + DIM / 2;
        for (int dp = lane; dp < DIM / 2; dp += 32) {
            float2 a = p0[dp];
            float2 c = p1[dp];
            s_dfT[k * DFS + dp] = pack2(c.x * i1 - a.x * i0, c.y * i1 - a.y * i0);
        }
    }
    __syncthreads();

    ull ts = 0ull;                  // tokensum for this thread's 2 dims (iter-0 fold)
    float tsx0 = 0.f, tsx1 = 0.f;

    for (int it = 0; it < ITERS; ++it) {
        ull bacc[KC];
        #pragma unroll
        for (int k = 0; k < KC; ++k) bacc[k] = 0ull;

        for (int c = 0; c < NCH; ++c) {
            const bool more = (c < NCH - 1) || (it < ITERS - 1);
            if (more) {
                const int nc = (c + 1) & 7;
                stage_chunk(s_tk + ((c + 1) & 1) * BUFULL,
                            tokbase + (size_t)nc * CHTOK * DIM, tid);
                asm volatile("cp.async.commit_group;");
                asm volatile("cp.async.wait_group 1;");
            } else {
                asm volatile("cp.async.wait_group 0;");
            }
            __syncthreads();

            const ull* buf = s_tk + (c & 1) * BUFULL;

            // ========== Phase A: register-tiled assignments ==========
            // Warp w owns j in [12w, 12w+12). Lane (tg=lane>>2, kg=lane&3)
            // owns tokens {tg, tg+8, tg+16, tg+24} x k {2kg, 2kg+1}.
            {
                const int tg = lane >> 2;
                const int kg = lane & 3;
                const ulonglong2* tb = (const ulonglong2*)buf;
                const ulonglong2* db = (const ulonglong2*)s_dfT;
                const int j0 = w * 12;
                ull ac00=0,ac01=0,ac10=0,ac11=0,ac20=0,ac21=0,ac30=0,ac31=0;
                #pragma unroll 4
                for (int j = 0; j < 12; ++j) {
                    const int jj = j0 + j;
                    ulonglong2 d0 = db[(2*kg    ) * 193 + jj];
                    ulonglong2 d1 = db[(2*kg + 1) * 193 + jj];
                    ulonglong2 t0 = tb[(tg      ) * 193 + jj];
                    ulonglong2 t1 = tb[(tg +  8 ) * 193 + jj];
                    ulonglong2 t2 = tb[(tg + 16 ) * 193 + jj];
                    ulonglong2 t3 = tb[(tg + 24 ) * 193 + jj];
                    ac00 = ffma2(t0.x, d0.x, ac00); ac00 = ffma2(t0.y, d0.y, ac00);
                    ac01 = ffma2(t0.x, d1.x, ac01); ac01 = ffma2(t0.y, d1.y, ac01);
                    ac10 = ffma2(t1.x, d0.x, ac10); ac10 = ffma2(t1.y, d0.y, ac10);
                    ac11 = ffma2(t1.x, d1.x, ac11); ac11 = ffma2(t1.y, d1.y, ac11);
                    ac20 = ffma2(t2.x, d0.x, ac20); ac20 = ffma2(t2.y, d0.y, ac20);
                    ac21 = ffma2(t2.x, d1.x, ac21); ac21 = ffma2(t2.y, d1.y, ac21);
                    ac30 = ffma2(t3.x, d0.x, ac30); ac30 = ffma2(t3.y, d0.y, ac30);
                    ac31 = ffma2(t3.x, d1.x, ac31); ac31 = ffma2(t3.y, d1.y, ac31);
                }
                float p[8];
                {
                    float x, y;
                    unpack2(ac00, x, y); p[0] = x + y;
                    unpack2(ac01, x, y); p[1] = x + y;
                    unpack2(ac10, x, y); p[2] = x + y;
                    unpack2(ac11, x, y); p[3] = x + y;
                    unpack2(ac20, x, y); p[4] = x + y;
                    unpack2(ac21, x, y); p[5] = x + y;
                    unpack2(ac30, x, y); p[6] = x + y;
                    unpack2(ac31, x, y); p[7] = x + y;
                }
                // 4 fixed-order reduction rounds into 4 slices (deterministic)
                const int wg    = w >> 2;
                const int slice = w & 3;
                float2* red = (float2*)(s_red + slice * 256);
                const int pos = 4 * tg + kg;        // float2 index 0..31
                if (wg == 3) {
                    #pragma unroll
                    for (int i = 0; i < 4; ++i)
                        red[pos + 32*i] = make_float2(p[2*i], p[2*i+1]);
                }
                __syncthreads();
                if (wg == 2) {
                    #pragma unroll
                    for (int i = 0; i < 4; ++i) {
                        float2 v = red[pos + 32*i];
                        red[pos + 32*i] = make_float2(v.x + p[2*i], v.y + p[2*i+1]);
                    }
                }
                __syncthreads();
                if (wg == 1) {
                    #pragma unroll
                    for (int i = 0; i < 4; ++i) {
                        float2 v = red[pos + 32*i];
                        red[pos + 32*i] = make_float2(v.x + p[2*i], v.y + p[2*i+1]);
                    }
                }
                __syncthreads();
                if (wg == 0) {
                    #pragma unroll
                    for (int i = 0; i < 4; ++i) {
                        float2 v = red[pos + 32*i];
                        red[pos + 32*i] = make_float2(v.x + p[2*i], v.y + p[2*i+1]);
                    }
                }
                __syncthreads();
                // final left-fold; thread tid<256 = (token = tid>>3, k = tid&7)
                if (tid < 256) {
                    float dot = ((s_red[tid] + s_red[256 + tid])
                                 + s_red[512 + tid]) + s_red[768 + tid];
                    const float af = dot > 0.f ? 1.f : 0.f;
                    s_a2[tid] = pack2(af, af);
                    if (it == ITERS - 1)
                        out_assign[((size_t)b * NTOK + c * CHTOK + (tid >> 3)) * KC + (tid & 7)] = af;
                }
            }
            __syncthreads();

            // ========== Phase B: thread (tid<384) owns dims [2tid, 2tid+2) ==========
            if (tid < 384) {
                #pragma unroll 4
                for (int n = 0; n < CHTOK; ++n) {
                    ull t = buf[n * TKS + tid];
                    const ulonglong2* q = (const ulonglong2*)(s_a2 + n * KC);
                    ulonglong2 m01 = q[0], m23 = q[1], m45 = q[2], m67 = q[3];
                    bacc[0] = ffma2(t, m01.x, bacc[0]);
                    bacc[1] = ffma2(t, m01.y, bacc[1]);
                    bacc[2] = ffma2(t, m23.x, bacc[2]);
                    bacc[3] = ffma2(t, m23.y, bacc[3]);
                    bacc[4] = ffma2(t, m45.x, bacc[4]);
                    bacc[5] = ffma2(t, m45.y, bacc[5]);
                    bacc[6] = ffma2(t, m67.x, bacc[6]);
                    bacc[7] = ffma2(t, m67.y, bacc[7]);
                    if (it == 0) ts = fadd2(ts, t);
                }
            }
            __syncthreads();
        }

        if (it == 0) unpack2(ts, tsx0, tsx1);

        // ---------- norms (deterministic reduction over 384 dim-owners) ----------
        float ssl[16];
        #pragma unroll
        for (int i = 0; i < 16; ++i) ssl[i] = 0.f;
        if (tid < 384) {
            #pragma unroll
            for (int k = 0; k < KC; ++k) {
                float x0, x1;
                unpack2(bacc[k], x0, x1);
                ssl[k] = x0*x0 + x1*x1;
                float y0 = tsx0 - x0, y1 = tsx1 - x1;
                ssl[8 + k] = y0*y0 + y1*y1;
            }
        }
        #pragma unroll
        for (int i = 0; i < 16; ++i) {
            float v = ssl[i];
            #pragma unroll
            for (int off = 16; off; off >>= 1)
                v += __shfl_down_sync(0xffffffffu, v, off);
            if (lane == 0 && w < 12) s_part[w][i] = v;
        }
        __syncthreads();
        if (tid < 16) {
            float v = 0.f;
            #pragma unroll
            for (int j = 0; j < 12; ++j) v += s_part[j][tid];   // fixed left fold
            s_inv[tid] = 1.f / fmaxf(sqrtf(v), 1e-12f);
        }
        __syncthreads();

        // ---------- next diff = c1*inv1 - c0*inv0 ----------
        if (tid < 384) {
            #pragma unroll
            for (int k = 0; k < KC; ++k) {
                const float i1 = s_inv[k], i0 = s_inv[8 + k];
                float x0, x1;
                unpack2(bacc[k], x0, x1);
                const float y0 = tsx0 - x0, y1 = tsx1 - x1;
                s_dfT[k * DFS + tid] = pack2(x0*i1 - y0*i0, x1*i1 - y1*i0);
            }
            if (it == ITERS - 1 && tid == 0) {
                // c0hat[k][0] -> fixed-point deterministic scatter bins
                #pragma unroll
                for (int k = 0; k < KC; ++k) {
                    float x0, x1;
                    unpack2(bacc[k], x0, x1);
                    double v = (double)((tsx0 - x0) * s_inv[8 + k]);
                    long long q = llrint(v * FXSCALE);
                    atomicAdd(&g_acc[topk[b * KC + k]], (ull)q);
                }
            }
        }
        __syncthreads();
    }
}

// =====================================================================
// Kernel 2: vc_new = l2norm(vc with delta at [v,0,0]) — warp-per-row.
// Each warp owns one (v,c) row: 6 float4/lane, xor-butterfly reduce,
// no block barriers. c=0 warp also consumes+resets g_acc[v]
// (replay-invariant: bins return to zero every launch).
// =====================================================================
__global__ __launch_bounds__(256)
void vcnew_kernel(const float* __restrict__ vc, float* __restrict__ out)
{
    const int gw   = (blockIdx.x * 256 + threadIdx.x) >> 5;   // global warp = row id
    const int lane = threadIdx.x & 31;
    if (gw >= VCNT * 2) return;
    const int v = gw >> 1;
    const int c = gw & 1;

    const float4* src = (const float4*)(vc + (size_t)gw * DIM);
    float4 x[6];
    #pragma unroll
    for (int i = 0; i < 6; ++i) x[i] = src[lane + 32 * i];   // MLP 6, coalesced

    if (c == 0 && lane == 0) {
        x[0].x += (float)((double)(long long)g_acc[v] * INV_FXSCALE);
        g_acc[v] = 0ull;                                     // reset for next replay
    }

    float ss = 0.f;
    #pragma unroll
    for (int i = 0; i < 6; ++i)
        ss += (x[i].x*x[i].x + x[i].y*x[i].y) + (x[i].z*x[i].z + x[i].w*x[i].w);
    #pragma unroll
    for (int off = 16; off; off >>= 1)
        ss += __shfl_xor_sync(0xffffffffu, ss, off);         // butterfly: all lanes

    const float sc = 1.f / fmaxf(sqrtf(ss), 1e-12f);
    float4* dst = (float4*)(out + (size_t)gw * DIM);
    #pragma unroll
    for (int i = 0; i < 6; ++i)
        dst[lane + 32 * i] = make_float4(x[i].x * sc, x[i].y * sc,
                                         x[i].z * sc, x[i].w * sc);
}

// =====================================================================
extern "C" void kernel_launch(void* const* d_in, const int* in_sizes, int n_in,
                              void* d_out, int out_size)
{
    const float* tokens = nullptr;
    const float* vc     = nullptr;
    const int*   topk   = nullptr;
    for (int i = 0; i < n_in; ++i) {
        if (in_sizes[i] == BATCH * NFULL * DIM)      tokens = (const float*)d_in[i];
        else if (in_sizes[i] == VCNT * 2 * DIM)      vc     = (const float*)d_in[i];
        else if (in_sizes[i] == BATCH * KC)          topk   = (const int*)d_in[i];
    }
    float* out = (float*)d_out;   // [assignments (256,256,8) | vc_new (10000,2,768)]

    static bool attr_set = false;
    if (!attr_set) {
        cudaFuncSetAttribute(kmeans_kernel,
                             cudaFuncAttributeMaxDynamicSharedMemorySize, KM_SMEM);
        attr_set = true;
    }

    kmeans_kernel<<<BATCH, NTHREADS, KM_SMEM>>>(tokens, vc, topk, out);
    vcnew_kernel<<<(VCNT * 2 * 32 + 255) / 256, 256>>>(vc, out + (size_t)BATCH * NTOK * KC);
}

// round 15
// speedup vs baseline: 1.8594x; 1.8594x over previous
#include <cuda_runtime.h>

typedef unsigned long long ull;

#define BATCH 256
#define NTOK  256
#define NFULL 257
#define DIM   768
#define KC    8
#define VCNT  10000
#define ITERS 4
#define NTHREADS 512

#define CHTOK 32                 /* tokens per smem chunk */
#define NCH   8                  /* chunks per pass */
#define TKS   386                /* ull stride per token row (conflict-free banking) */
#define DFS   386                /* ull stride per diff row */
#define BUFULL (CHTOK * TKS)     /* 12352 ull per stage buffer */

/* dynamic smem layout (bytes) — total 228288 < 232448 cap */
#define OFF_TK   0
#define SZ_TK    (2 * BUFULL * 8)          /* 197632 : double-buffered token chunks */
#define OFF_DFT  (OFF_TK + SZ_TK)          /* 197632 */
#define SZ_DFT   (KC * DFS * 8)            /* 24704  : diff[k][dp] */
#define OFF_A1   (OFF_DFT + SZ_DFT)        /* 222336 */
#define SZ_A1    (CHTOK * KC * 4)          /* 1024   : assignments as plain f32 */
#define OFF_RED  (OFF_A1 + SZ_A1)          /* 223360 */
#define SZ_RED   (4 * 256 * 4)             /* 4096   : phase-A cross-warp partials */
#define OFF_PART (OFF_RED + SZ_RED)        /* 227456 */
#define SZ_PART  (12 * 16 * 4)             /* 768 */
#define OFF_INV  (OFF_PART + SZ_PART)      /* 228224 */
#define KM_SMEM  (OFF_INV + 64)            /* 228288 */

#define FXSCALE     1099511627776.0        /* 2^40 */
#define INV_FXSCALE (1.0 / 1099511627776.0)

__device__ ull g_acc[VCNT];   // fixed-point scatter bins (integer adds: deterministic)

// ---------------- packed f32x2 helpers (sm_103a) ----------------
__device__ __forceinline__ ull ffma2(ull a, ull b, ull c) {
    ull d; asm("fma.rn.f32x2 %0, %1, %2, %3;" : "=l"(d) : "l"(a), "l"(b), "l"(c)); return d;
}
__device__ __forceinline__ ull fadd2(ull a, ull b) {
    ull d; asm("add.rn.f32x2 %0, %1, %2;" : "=l"(d) : "l"(a), "l"(b)); return d;
}
__device__ __forceinline__ ull pack2(float x, float y) {
    ull r; asm("mov.b64 %0, {%1, %2};" : "=l"(r) : "f"(x), "f"(y)); return r;
}
__device__ __forceinline__ void unpack2(ull v, float& x, float& y) {
    asm("mov.b64 {%0, %1}, %2;" : "=f"(x), "=f"(y) : "l"(v));
}

// coalesced cp.async stage of one 32-token chunk (32 x 768 floats), 512 threads
__device__ __forceinline__ void stage_chunk(ull* dstbuf, const float* src, int tid) {
    #pragma unroll
    for (int i = 0; i < 12; ++i) {
        int f = tid + NTHREADS * i;       // 0..6143 16B-segments
        int r = f / 192;                  // token row 0..31
        int s = f - r * 192;              // segment within row
        unsigned d = (unsigned)__cvta_generic_to_shared(dstbuf + r * TKS + s * 2);
        asm volatile("cp.async.cg.shared.global [%0], [%1], 16;"
                     :: "r"(d), "l"(src + (size_t)r * DIM + s * 4));
    }
}

// =====================================================================
// Kernel 1: fused per-batch k-means. 512 threads, 1 block/batch,
// ~228KB dyn smem -> 1 block/SM. Phase B masks loaded as f32 (halved
// broadcast traffic), pairs built in registers.
// =====================================================================
__global__ void __launch_bounds__(NTHREADS, 1)
kmeans_kernel(const float* __restrict__ tokens,
              const float* __restrict__ vc,
              const int*   __restrict__ topk,
              float*       __restrict__ out_assign)
{
    extern __shared__ __align__(16) char smem[];
    ull*   s_tk  = (ull*)(smem + OFF_TK);
    ull*   s_dfT = (ull*)(smem + OFF_DFT);
    float* s_a1  = (float*)(smem + OFF_A1);
    float* s_red = (float*)(smem + OFF_RED);
    float (*s_part)[16] = (float(*)[16])(smem + OFF_PART);
    float* s_inv = (float*)(smem + OFF_INV);

    const int b    = blockIdx.x;
    const int tid  = threadIdx.x;
    const int lane = tid & 31;
    const int w    = tid >> 5;

    const float* tokbase = tokens + ((size_t)b * NFULL + 1) * DIM;

    // prefetch chunk 0 while building the initial diff matrix
    stage_chunk(s_tk, tokbase, tid);
    asm volatile("cp.async.commit_group;");

    // initial diff = c1hat - c0hat (warps 0-7: warp w -> k=w)
    if (w < 8) {
        const int k   = w;
        const int idx = topk[b * KC + k];
        const float4* r0 = (const float4*)(vc + (size_t)idx * 2 * DIM);
        const float4* r1 = r0 + DIM / 4;
        float ss0 = 0.f, ss1 = 0.f;
        for (int j = lane; j < DIM / 4; j += 32) {
            float4 a = r0[j]; ss0 += a.x*a.x + a.y*a.y + a.z*a.z + a.w*a.w;
            float4 c = r1[j]; ss1 += c.x*c.x + c.y*c.y + c.z*c.z + c.w*c.w;
        }
        #pragma unroll
        for (int off = 16; off; off >>= 1) {
            ss0 += __shfl_down_sync(0xffffffffu, ss0, off);
            ss1 += __shfl_down_sync(0xffffffffu, ss1, off);
        }
        ss0 = __shfl_sync(0xffffffffu, ss0, 0);
        ss1 = __shfl_sync(0xffffffffu, ss1, 0);
        const float i0 = 1.f / fmaxf(sqrtf(ss0), 1e-12f);
        const float i1 = 1.f / fmaxf(sqrtf(ss1), 1e-12f);
        const float2* p0 = (const float2*)(vc + (size_t)idx * 2 * DIM);
        const float2* p1 = p0 + DIM / 2;
        for (int dp = lane; dp < DIM / 2; dp += 32) {
            float2 a = p0[dp];
            float2 c = p1[dp];
            s_dfT[k * DFS + dp] = pack2(c.x * i1 - a.x * i0, c.y * i1 - a.y * i0);
        }
    }
    __syncthreads();

    ull ts = 0ull;                  // tokensum for this thread's 2 dims (iter-0 fold)
    float tsx0 = 0.f, tsx1 = 0.f;

    for (int it = 0; it < ITERS; ++it) {
        ull bacc[KC];
        #pragma unroll
        for (int k = 0; k < KC; ++k) bacc[k] = 0ull;

        for (int c = 0; c < NCH; ++c) {
            const bool more = (c < NCH - 1) || (it < ITERS - 1);
            if (more) {
                const int nc = (c + 1) & 7;
                stage_chunk(s_tk + ((c + 1) & 1) * BUFULL,
                            tokbase + (size_t)nc * CHTOK * DIM, tid);
                asm volatile("cp.async.commit_group;");
                asm volatile("cp.async.wait_group 1;");
            } else {
                asm volatile("cp.async.wait_group 0;");
            }
            __syncthreads();

            const ull* buf = s_tk + (c & 1) * BUFULL;

            // ========== Phase A: register-tiled assignments ==========
            // Warp w owns j in [12w, 12w+12). Lane (tg=lane>>2, kg=lane&3)
            // owns tokens {tg, tg+8, tg+16, tg+24} x k {2kg, 2kg+1}.
            {
                const int tg = lane >> 2;
                const int kg = lane & 3;
                const ulonglong2* tb = (const ulonglong2*)buf;
                const ulonglong2* db = (const ulonglong2*)s_dfT;
                const int j0 = w * 12;
                ull ac00=0,ac01=0,ac10=0,ac11=0,ac20=0,ac21=0,ac30=0,ac31=0;
                #pragma unroll 4
                for (int j = 0; j < 12; ++j) {
                    const int jj = j0 + j;
                    ulonglong2 d0 = db[(2*kg    ) * 193 + jj];
                    ulonglong2 d1 = db[(2*kg + 1) * 193 + jj];
                    ulonglong2 t0 = tb[(tg      ) * 193 + jj];
                    ulonglong2 t1 = tb[(tg +  8 ) * 193 + jj];
                    ulonglong2 t2 = tb[(tg + 16 ) * 193 + jj];
                    ulonglong2 t3 = tb[(tg + 24 ) * 193 + jj];
                    ac00 = ffma2(t0.x, d0.x, ac00); ac00 = ffma2(t0.y, d0.y, ac00);
                    ac01 = ffma2(t0.x, d1.x, ac01); ac01 = ffma2(t0.y, d1.y, ac01);
                    ac10 = ffma2(t1.x, d0.x, ac10); ac10 = ffma2(t1.y, d0.y, ac10);
                    ac11 = ffma2(t1.x, d1.x, ac11); ac11 = ffma2(t1.y, d1.y, ac11);
                    ac20 = ffma2(t2.x, d0.x, ac20); ac20 = ffma2(t2.y, d0.y, ac20);
                    ac21 = ffma2(t2.x, d1.x, ac21); ac21 = ffma2(t2.y, d1.y, ac21);
                    ac30 = ffma2(t3.x, d0.x, ac30); ac30 = ffma2(t3.y, d0.y, ac30);
                    ac31 = ffma2(t3.x, d1.x, ac31); ac31 = ffma2(t3.y, d1.y, ac31);
                }
                float p[8];
                {
                    float x, y;
                    unpack2(ac00, x, y); p[0] = x + y;
                    unpack2(ac01, x, y); p[1] = x + y;
                    unpack2(ac10, x, y); p[2] = x + y;
                    unpack2(ac11, x, y); p[3] = x + y;
                    unpack2(ac20, x, y); p[4] = x + y;
                    unpack2(ac21, x, y); p[5] = x + y;
                    unpack2(ac30, x, y); p[6] = x + y;
                    unpack2(ac31, x, y); p[7] = x + y;
                }
                // 4 fixed-order reduction rounds into 4 slices (deterministic)
                const int wg    = w >> 2;
                const int slice = w & 3;
                float2* red = (float2*)(s_red + slice * 256);
                const int pos = 4 * tg + kg;        // float2 index 0..31
                if (wg == 3) {
                    #pragma unroll
                    for (int i = 0; i < 4; ++i)
                        red[pos + 32*i] = make_float2(p[2*i], p[2*i+1]);
                }
                __syncthreads();
                if (wg == 2) {
                    #pragma unroll
                    for (int i = 0; i < 4; ++i) {
                        float2 v = red[pos + 32*i];
                        red[pos + 32*i] = make_float2(v.x + p[2*i], v.y + p[2*i+1]);
                    }
                }
                __syncthreads();
                if (wg == 1) {
                    #pragma unroll
                    for (int i = 0; i < 4; ++i) {
                        float2 v = red[pos + 32*i];
                        red[pos + 32*i] = make_float2(v.x + p[2*i], v.y + p[2*i+1]);
                    }
                }
                __syncthreads();
                if (wg == 0) {
                    #pragma unroll
                    for (int i = 0; i < 4; ++i) {
                        float2 v = red[pos + 32*i];
                        red[pos + 32*i] = make_float2(v.x + p[2*i], v.y + p[2*i+1]);
                    }
                }
                __syncthreads();
                // final left-fold; thread tid<256 = (token = tid>>3, k = tid&7)
                if (tid < 256) {
                    float dot = ((s_red[tid] + s_red[256 + tid])
                                 + s_red[512 + tid]) + s_red[768 + tid];
                    const float af = dot > 0.f ? 1.f : 0.f;
                    s_a1[tid] = af;                 // plain f32 (row-major [token][k])
                    if (it == ITERS - 1)
                        out_assign[((size_t)b * NTOK + c * CHTOK + (tid >> 3)) * KC + (tid & 7)] = af;
                }
            }
            __syncthreads();

            // ========== Phase B: thread (tid<384) owns dims [2tid, 2tid+2) ==========
            // Masks: 2 broadcast LDS.128 per token (f32), pairs built in regs.
            if (tid < 384) {
                #pragma unroll 4
                for (int n = 0; n < CHTOK; ++n) {
                    ull t = buf[n * TKS + tid];
                    float4 qa = *(const float4*)(s_a1 + n * KC);
                    float4 qb = *(const float4*)(s_a1 + n * KC + 4);
                    bacc[0] = ffma2(t, pack2(qa.x, qa.x), bacc[0]);
                    bacc[1] = ffma2(t, pack2(qa.y, qa.y), bacc[1]);
                    bacc[2] = ffma2(t, pack2(qa.z, qa.z), bacc[2]);
                    bacc[3] = ffma2(t, pack2(qa.w, qa.w), bacc[3]);
                    bacc[4] = ffma2(t, pack2(qb.x, qb.x), bacc[4]);
                    bacc[5] = ffma2(t, pack2(qb.y, qb.y), bacc[5]);
                    bacc[6] = ffma2(t, pack2(qb.z, qb.z), bacc[6]);
                    bacc[7] = ffma2(t, pack2(qb.w, qb.w), bacc[7]);
                    if (it == 0) ts = fadd2(ts, t);
                }
            }
            __syncthreads();
        }

        if (it == 0) unpack2(ts, tsx0, tsx1);

        // ---------- norms (deterministic reduction over 384 dim-owners) ----------
        float ssl[16];
        #pragma unroll
        for (int i = 0; i < 16; ++i) ssl[i] = 0.f;
        if (tid < 384) {
            #pragma unroll
            for (int k = 0; k < KC; ++k) {
                float x0, x1;
                unpack2(bacc[k], x0, x1);
                ssl[k] = x0*x0 + x1*x1;
                float y0 = tsx0 - x0, y1 = tsx1 - x1;
                ssl[8 + k] = y0*y0 + y1*y1;
            }
        }
        #pragma unroll
        for (int i = 0; i < 16; ++i) {
            float v = ssl[i];
            #pragma unroll
            for (int off = 16; off; off >>= 1)
                v += __shfl_down_sync(0xffffffffu, v, off);
            if (lane == 0 && w < 12) s_part[w][i] = v;
        }
        __syncthreads();
        if (tid < 16) {
            float v = 0.f;
            #pragma unroll
            for (int j = 0; j < 12; ++j) v += s_part[j][tid];   // fixed left fold
            s_inv[tid] = 1.f / fmaxf(sqrtf(v), 1e-12f);
        }
        __syncthreads();

        // ---------- next diff = c1*inv1 - c0*inv0 ----------
        if (tid < 384) {
            #pragma unroll
            for (int k = 0; k < KC; ++k) {
                const float i1 = s_inv[k], i0 = s_inv[8 + k];
                float x0, x1;
                unpack2(bacc[k], x0, x1);
                const float y0 = tsx0 - x0, y1 = tsx1 - x1;
                s_dfT[k * DFS + tid] = pack2(x0*i1 - y0*i0, x1*i1 - y1*i0);
            }
            if (it == ITERS - 1 && tid == 0) {
                // c0hat[k][0] -> fixed-point deterministic scatter bins
                #pragma unroll
                for (int k = 0; k < KC; ++k) {
                    float x0, x1;
                    unpack2(bacc[k], x0, x1);
                    double v = (double)((tsx0 - x0) * s_inv[8 + k]);
                    long long q = llrint(v * FXSCALE);
                    atomicAdd(&g_acc[topk[b * KC + k]], (ull)q);
                }
            }
        }
        __syncthreads();
    }
}

// =====================================================================
// Kernel 2: vc_new = l2norm(vc with delta at [v,0,0]) — warp-per-row.
// 6 float4/lane, xor-butterfly reduce, no block barriers. c=0 warp
// consumes + resets g_acc[v] (replay-invariant).
// =====================================================================
__global__ __launch_bounds__(256)
void vcnew_kernel(const float* __restrict__ vc, float* __restrict__ out)
{
    const int gw   = (blockIdx.x * 256 + threadIdx.x) >> 5;   // global warp = row id
    const int lane = threadIdx.x & 31;
    if (gw >= VCNT * 2) return;
    const int v = gw >> 1;
    const int c = gw & 1;

    const float4* src = (const float4*)(vc + (size_t)gw * DIM);
    float4 x[6];
    #pragma unroll
    for (int i = 0; i < 6; ++i) x[i] = src[lane + 32 * i];   // MLP 6, coalesced

    if (c == 0 && lane == 0) {
        x[0].x += (float)((double)(long long)g_acc[v] * INV_FXSCALE);
        g_acc[v] = 0ull;                                     // reset for next replay
    }

    float ss = 0.f;
    #pragma unroll
    for (int i = 0; i < 6; ++i)
        ss += (x[i].x*x[i].x + x[i].y*x[i].y) + (x[i].z*x[i].z + x[i].w*x[i].w);
    #pragma unroll
    for (int off = 16; off; off >>= 1)
        ss += __shfl_xor_sync(0xffffffffu, ss, off);         // butterfly: all lanes

    const float sc = 1.f / fmaxf(sqrtf(ss), 1e-12f);
    float4* dst = (float4*)(out + (size_t)gw * DIM);
    #pragma unroll
    for (int i = 0; i < 6; ++i)
        dst[lane + 32 * i] = make_float4(x[i].x * sc, x[i].y * sc,
                                         x[i].z * sc, x[i].w * sc);
}

// =====================================================================
extern "C" void kernel_launch(void* const* d_in, const int* in_sizes, int n_in,
                              void* d_out, int out_size)
{
    const float* tokens = nullptr;
    const float* vc     = nullptr;
    const int*   topk   = nullptr;
    for (int i = 0; i < n_in; ++i) {
        if (in_sizes[i] == BATCH * NFULL * DIM)      tokens = (const float*)d_in[i];
        else if (in_sizes[i] == VCNT * 2 * DIM)      vc     = (const float*)d_in[i];
        else if (in_sizes[i] == BATCH * KC)          topk   = (const int*)d_in[i];
    }
    float* out = (float*)d_out;   // [assignments (256,256,8) | vc_new (10000,2,768)]

    static bool attr_set = false;
    if (!attr_set) {
        cudaFuncSetAttribute(kmeans_kernel,
                             cudaFuncAttributeMaxDynamicSharedMemorySize, KM_SMEM);
        attr_set = true;
    }

    kmeans_kernel<<<BATCH, NTHREADS, KM_SMEM>>>(tokens, vc, topk, out);
    vcnew_kernel<<<(VCNT * 2 * 32 + 255) / 256, 256>>>(vc, out + (size_t)BATCH * NTOK * KC);
}